// round 16
// baseline (speedup 1.0000x reference)
#include <cuda_runtime.h>
#include <cstdint>

typedef unsigned long long ull;

#define B_      2
#define L_      4096
#define HIDDEN  512
#define HEADS   8
#define HD      64
#define PREFIX  1
#define M_ROWS  (B_ * L_)        // 8192
#define CC_SCALE 0.18033688011112042f   // (1/8) * log2(e), folded into Q
#define ONESH2  0x3C003C00u             // fp16x2 {1.0, 1.0}

// ---- fp16 storage (allocation-free: __device__ globals) ----
__device__ __align__(16) uint16_t gx_f16[M_ROWS * HIDDEN];
__device__ __align__(16) uint16_t gwi_f16[3 * HIDDEN * HIDDEN];
__device__ __align__(16) uint16_t gwo_f16[HIDDEN * HIDDEN];
__device__ __align__(16) uint16_t gq_f16[M_ROWS * HIDDEN];
__device__ __align__(16) uint16_t gk_f16[M_ROWS * HIDDEN];
__device__ __align__(16) uint16_t gv_f16[M_ROWS * HIDDEN];
__device__ __align__(16) uint16_t gctx_f16[M_ROWS * HIDDEN];

// ============================================================
// helpers
// ============================================================
__device__ __forceinline__ uint32_t smem_u32(const void* p) {
    uint32_t a;
    asm("{ .reg .u64 t; cvta.to.shared.u64 t, %1; cvt.u32.u64 %0, t; }" : "=r"(a) : "l"(p));
    return a;
}
__device__ __forceinline__ uint32_t cvt_f16x2(float lo, float hi) {
    uint32_t r; asm("cvt.rn.f16x2.f32 %0,%1,%2;" : "=r"(r) : "f"(hi), "f"(lo)); return r;
}
__device__ __forceinline__ float ex2f(float x) {
    float r; asm("ex2.approx.f32 %0,%1;" : "=f"(r) : "f"(x)); return r;
}
__device__ __forceinline__ uint32_t swz128(uint32_t o) { return o ^ ((o >> 3) & 0x70u); }

__device__ __forceinline__ void cp16(uint32_t dst, const void* src) {
    asm volatile("cp.async.cg.shared.global [%0], [%1], 16;" :: "r"(dst), "l"(src) : "memory");
}
__device__ __forceinline__ void cp_commit() {
    asm volatile("cp.async.commit_group;" ::: "memory");
}
template <int N> __device__ __forceinline__ void cp_wait() {
    asm volatile("cp.async.wait_group %0;" :: "n"(N) : "memory");
}

__device__ __forceinline__ void ldsm4(uint32_t& r0, uint32_t& r1, uint32_t& r2, uint32_t& r3,
                                      uint32_t addr) {
    asm volatile("ldmatrix.sync.aligned.m8n8.x4.shared.b16 {%0,%1,%2,%3}, [%4];"
                 : "=r"(r0), "=r"(r1), "=r"(r2), "=r"(r3) : "r"(addr));
}
__device__ __forceinline__ void ldsm4t(uint32_t& r0, uint32_t& r1, uint32_t& r2, uint32_t& r3,
                                       uint32_t addr) {
    asm volatile("ldmatrix.sync.aligned.m8n8.x4.trans.shared.b16 {%0,%1,%2,%3}, [%4];"
                 : "=r"(r0), "=r"(r1), "=r"(r2), "=r"(r3) : "r"(addr));
}
__device__ __forceinline__ void mma_f16(float* c, const uint32_t* a, uint32_t b0, uint32_t b1) {
    asm volatile(
        "mma.sync.aligned.m16n8k16.row.col.f32.f16.f16.f32 "
        "{%0,%1,%2,%3},{%4,%5,%6,%7},{%8,%9},{%0,%1,%2,%3};"
        : "+f"(c[0]), "+f"(c[1]), "+f"(c[2]), "+f"(c[3])
        : "r"(a[0]), "r"(a[1]), "r"(a[2]), "r"(a[3]), "r"(b0), "r"(b1));
}

// ============================================================
// conversion kernels: fp32 -> fp16
// ============================================================
__global__ __launch_bounds__(256) void conv_x_kernel(const float* __restrict__ x)
{
    size_t gid = (size_t)blockIdx.x * 256 + threadIdx.x;
    size_t i = gid * 4;
    float4 v = *(const float4*)(x + i);
    uint2 H;
    H.x = cvt_f16x2(v.x, v.y);
    H.y = cvt_f16x2(v.z, v.w);
    *(uint2*)(gx_f16 + i) = H;
}

__global__ __launch_bounds__(256) void conv_wT_kernel(const float* __restrict__ w,
                                                      int K, int N, int which)
{
    __shared__ float t[32][33];
    uint16_t* dst = which ? gwo_f16 : gwi_f16;
    int n0 = blockIdx.x * 32, k0 = blockIdx.y * 32;
    int tx = threadIdx.x & 31, ty = threadIdx.x >> 5;
#pragma unroll
    for (int i = 0; i < 4; i++)
        t[ty + 8 * i][tx] = w[(size_t)(k0 + ty + 8 * i) * N + n0 + tx];
    __syncthreads();
#pragma unroll
    for (int i = 0; i < 4; i++) {
        int nn = ty + 8 * i;
        float v = t[tx][nn];
        uint16_t h;
        asm("cvt.rn.f16.f32 %0,%1;" : "=h"(h) : "f"(v));
        dst[(size_t)(n0 + nn) * K + k0 + tx] = h;
    }
}

// ============================================================
// GEMM fp16: CTA tile 128x128, 256 thr, warp tile 32x64,
// k-chunk 64 (swz128 rows), 3-stage ring + depth-1 prefetch,
// ONE sync per chunk (8 total), 2 CTA/SM.
// Stage (32KB): {A 0..16K, B 16K..32K}.
// ============================================================
#define GSTAGE 32768u

template <int MODE>
__global__ __launch_bounds__(256, 2) void gemm_f16_kernel(
    const float* __restrict__ bias, float* __restrict__ Cout)
{
    extern __shared__ char smp[];
    const uint32_t sbase = smem_u32(smp);
    int tid = threadIdx.x;
    int lane = tid & 31, w = tid >> 5;
    int wm = w >> 1, wn = w & 1;     // 4 x 2 warp grid, warp tile 32x64
    int bm = blockIdx.y, bn = blockIdx.x;

    const uint16_t* A = (MODE == 0) ? gx_f16 : gctx_f16;
    const uint16_t* Bw = (MODE == 0) ? gwi_f16 : gwo_f16;

    // loaders: 2 thr/row (128B row), 4 16B-groups per thread
    int r = tid >> 1, g0 = (tid & 1) * 4;
    size_t aoff = (size_t)(bm * 128 + r) * HIDDEN;
    size_t boff = (size_t)(bn * 128 + r) * HIDDEN;

    float acc[2][8][4];
#pragma unroll
    for (int i = 0; i < 2; i++)
#pragma unroll
        for (int j = 0; j < 8; j++)
#pragma unroll
            for (int e = 0; e < 4; e++) acc[i][j][e] = 0.f;

#define ISSUE_CHUNK(kc, buf) do {                                               \
        uint32_t dst = sbase + (uint32_t)(buf) * GSTAGE;                         \
        const uint16_t* ap = A  + aoff + (kc) * 64;                              \
        const uint16_t* bp = Bw + boff + (kc) * 64;                              \
        _Pragma("unroll")                                                        \
        for (int i = 0; i < 4; i++) {                                            \
            uint32_t so = swz128((uint32_t)r * 128u + (uint32_t)(g0 + i) * 16u); \
            cp16(dst + so,           ap + (g0 + i) * 8);                         \
            cp16(dst + 16384u + so,  bp + (g0 + i) * 8);                         \
        }                                                                        \
        cp_commit();                                                             \
    } while (0)

    ISSUE_CHUNK(0, 0);

    const int NK = HIDDEN / 64;   // 8 chunks
    int rb = 0;                   // read buffer = kc % 3
    for (int kc = 0; kc < NK; kc++) {
        if (kc + 1 < NK) {
            int wb = rb + 1; if (wb == 3) wb = 0;
            ISSUE_CHUNK(kc + 1, wb);
            cp_wait<1>();
        } else {
            cp_wait<0>();
        }
        __syncthreads();   // single barrier per chunk (3-buf ring)

        uint32_t abase = sbase + (uint32_t)rb * GSTAGE;
        uint32_t bbase = abase + 16384u;
#pragma unroll
        for (int ks = 0; ks < 4; ks++) {
            uint32_t ah[2][4];
#pragma unroll
            for (int mi = 0; mi < 2; mi++) {
                uint32_t off = swz128((uint32_t)(wm * 32 + mi * 16 + (lane & 15)) * 128u
                                      + (uint32_t)(ks * 32 + ((lane & 16) ? 16 : 0)));
                ldsm4(ah[mi][0], ah[mi][1], ah[mi][2], ah[mi][3], abase + off);
            }
#pragma unroll
            for (int np = 0; np < 4; np++) {
                uint32_t boffs = swz128((uint32_t)(wn * 64 + np * 16 + (lane & 7)
                                                   + ((lane & 16) ? 8 : 0)) * 128u
                                        + (uint32_t)(ks * 32 + ((lane & 8) ? 16 : 0)));
                uint32_t b0, b1, b2, b3;
                ldsm4(b0, b1, b2, b3, bbase + boffs);
#pragma unroll
                for (int mi = 0; mi < 2; mi++) {
                    mma_f16(acc[mi][2 * np],     ah[mi], b0, b1);
                    mma_f16(acc[mi][2 * np + 1], ah[mi], b2, b3);
                }
            }
        }
        rb = rb + 1; if (rb == 3) rb = 0;
    }
#undef ISSUE_CHUNK

    // ---- epilogue ----
#pragma unroll
    for (int mi = 0; mi < 2; mi++) {
        int r0 = bm * 128 + wm * 32 + mi * 16 + (lane >> 2);
#pragma unroll
        for (int nj = 0; nj < 8; nj++) {
            int c0 = bn * 128 + wn * 64 + nj * 8 + 2 * (lane & 3);
            float bb0 = __ldg(bias + c0), bb1 = __ldg(bias + c0 + 1);
            float v0 = acc[mi][nj][0] + bb0, v1 = acc[mi][nj][1] + bb1;
            float v2 = acc[mi][nj][2] + bb0, v3 = acc[mi][nj][3] + bb1;
            if (MODE == 0) {
                int which = c0 >> 9, h = (c0 >> 6) & 7, d = c0 & 63;
                uint16_t* dq = (which == 0) ? gq_f16 : (which == 1) ? gk_f16 : gv_f16;
                if (which == 0) {   // fold softmax scale*log2e into Q
                    v0 *= CC_SCALE; v1 *= CC_SCALE; v2 *= CC_SCALE; v3 *= CC_SCALE;
                }
                int b = r0 >> 12;
                size_t base0 = ((size_t)((b * 8 + h) * L_ + (r0 & 4095))) * 64 + d;
                size_t base1 = base0 + 8 * 64;
                *(uint32_t*)(dq + base0) = cvt_f16x2(v0, v1);
                *(uint32_t*)(dq + base1) = cvt_f16x2(v2, v3);
            } else {
                *(float2*)(Cout + (size_t)r0 * HIDDEN + c0) = make_float2(v0, v1);
                *(float2*)(Cout + (size_t)(r0 + 8) * HIDDEN + c0) = make_float2(v2, v3);
            }
        }
    }
}

// ============================================================
// Attention fp16 (Q pre-scaled): 128-key tiles, 3-buffer ring
// (3 x 32KB: K 16KB + V 16KB), Q overlaid on buf2 (written first
// at kt=1, after all Q ldsm). ONE sync per tile. 96KB, 2 CTA/SM.
// ============================================================
#define SQ   65536u    // Q region == buf2 (safe overlay)
#define ATTN_SMEM 98304

__global__ __launch_bounds__(256, 2) void attn_mma_kernel()
{
    extern __shared__ char smp[];
    const uint32_t sbase = smem_u32(smp);
    int tid = threadIdx.x;
    int w = tid >> 5, lane = tid & 31;

    int bh = blockIdx.x;                            // b*8 + h
    int qt = (int)gridDim.y - 1 - (int)blockIdx.y;  // heavy tiles first
    int nkt = qt + 1;                               // 128-key tiles

    // K/V loaders: 128 threads each, 1 thr/row, 8 cp16 per thread
    int ct = tid & 127;
    const uint16_t* srckv = (tid < 128) ? gk_f16 : gv_f16;
    uint32_t dsel = (tid < 128) ? 0u : 16384u;

#define ISSUE_KV(kt, buf) do {                                                   \
        uint32_t dst = sbase + (uint32_t)(buf) * 32768u + dsel;                  \
        const uint16_t* sp = srckv + ((size_t)bh * L_ + (size_t)(kt) * 128 + ct) * 64; \
        _Pragma("unroll")                                                        \
        for (int i = 0; i < 8; i++) {                                            \
            uint32_t so = swz128((uint32_t)ct * 128u + (uint32_t)i * 16u);       \
            cp16(dst + so, sp + i * 8);                                          \
        }                                                                        \
        cp_commit();                                                             \
    } while (0)

    // Prologue: Q tile copy into buf2 region + first K/V issue into buf0
    {
        const uint4* q4 = (const uint4*)(gq_f16 + ((size_t)bh * L_ + (size_t)qt * 128 + (tid >> 1)) * 64);
        int qg0 = (tid & 1) * 4;
#pragma unroll
        for (int i = 0; i < 4; i++) {
            uint32_t so = swz128((uint32_t)(tid >> 1) * 128u + (uint32_t)(qg0 + i) * 16u);
            *(uint4*)(smp + SQ + so) = q4[qg0 + i];
        }
    }
    ISSUE_KV(0, 0);
    __syncthreads();

    int arow = 16 * w + (lane & 15);
    uint32_t qf[4][4];   // fp16 Q A-fragments (pre-scaled), resident whole kernel
    {
#pragma unroll
        for (int ks = 0; ks < 4; ks++) {
            uint32_t off = swz128((uint32_t)arow * 128u
                                  + (uint32_t)(ks * 32 + ((lane & 16) ? 16 : 0)));
            ldsm4(qf[ks][0], qf[ks][1], qf[ks][2], qf[ks][3], sbase + SQ + off);
        }
    }

    float oc[8][4];
#pragma unroll
    for (int n = 0; n < 8; n++)
#pragma unroll
        for (int j = 0; j < 4; j++) oc[n][j] = 0.f;
    float lsC[4] = {0.f, 0.f, 0.f, 0.f};   // row sums via ones-MMA

    int row0 = qt * 128 + 16 * w + (lane >> 2);
    int row1 = row0 + 8;

    int rbuf = 0;   // read buffer = kt % 3
    for (int kt = 0; kt < nkt; ++kt) {
        if (kt + 1 < nkt) {
            int wb = rbuf + 1; if (wb == 3) wb = 0;
            ISSUE_KV(kt + 1, wb);
            cp_wait<1>();
        } else {
            cp_wait<0>();
        }
        __syncthreads();   // single barrier per 128-key tile

        uint32_t kvb = sbase + (uint32_t)rbuf * 32768u;
        bool edge = (kt == 0) || (kt == qt);

#pragma unroll
        for (int half = 0; half < 2; half++) {
            // ---- S = Q K^T over 64 keys ----
            float sc[8][4];
#pragma unroll
            for (int n = 0; n < 8; n++)
#pragma unroll
                for (int j = 0; j < 4; j++) sc[n][j] = 0.f;

#pragma unroll
            for (int ks = 0; ks < 4; ks++) {
#pragma unroll
                for (int npp = 0; npp < 2; npp++) {
                    int key0 = half * 64 + (2 * npp) * 16 + (lane & 7) + ((lane & 16) ? 8 : 0);
                    uint32_t col = (uint32_t)(ks * 32 + ((lane & 8) ? 16 : 0));
                    uint32_t off0 = swz128((uint32_t)key0 * 128u + col);
                    uint32_t off1 = swz128((uint32_t)(key0 + 16) * 128u + col);
                    uint32_t b00, b01, b02, b03, b10, b11, b12, b13;
                    ldsm4(b00, b01, b02, b03, kvb + off0);
                    ldsm4(b10, b11, b12, b13, kvb + off1);
                    mma_f16(sc[4 * npp + 0], qf[ks], b00, b01);
                    mma_f16(sc[4 * npp + 1], qf[ks], b02, b03);
                    mma_f16(sc[4 * npp + 2], qf[ks], b10, b11);
                    mma_f16(sc[4 * npp + 3], qf[ks], b12, b13);
                }
            }

            // ---- masking: only on edge tiles, sentinel -100 ----
            if (edge) {
                int colb = kt * 128 + half * 64 + 2 * (lane & 3);
#pragma unroll
                for (int n = 0; n < 8; n++) {
                    int c0 = colb + 8 * n, c1 = c0 + 1;
                    if (!((c0 <= row0) && (c0 >= PREFIX || row0 < PREFIX))) sc[n][0] = -100.f;
                    if (!((c1 <= row0) && (c1 >= PREFIX || row0 < PREFIX))) sc[n][1] = -100.f;
                    if (!((c0 <= row1) && (c0 >= PREFIX || row1 < PREFIX))) sc[n][2] = -100.f;
                    if (!((c1 <= row1) && (c1 >= PREFIX || row1 < PREFIX))) sc[n][3] = -100.f;
                }
            }

            // ---- exp2 + pack + lsum(ones-MMA) + PV ----
#pragma unroll
            for (int t = 0; t < 4; t++) {
                uint32_t pf[4];
                pf[0] = cvt_f16x2(ex2f(sc[2 * t][0]),     ex2f(sc[2 * t][1]));
                pf[1] = cvt_f16x2(ex2f(sc[2 * t][2]),     ex2f(sc[2 * t][3]));
                pf[2] = cvt_f16x2(ex2f(sc[2 * t + 1][0]), ex2f(sc[2 * t + 1][1]));
                pf[3] = cvt_f16x2(ex2f(sc[2 * t + 1][2]), ex2f(sc[2 * t + 1][3]));
                mma_f16(lsC, pf, ONESH2, ONESH2);
                int key = half * 64 + t * 16 + (lane & 7) + ((lane & 8) ? 8 : 0);
#pragma unroll
                for (int dpp = 0; dpp < 2; dpp++) {
                    uint32_t col0 = (uint32_t)((2 * dpp) * 32 + ((lane & 16) ? 16 : 0));
                    uint32_t off0 = swz128((uint32_t)key * 128u + col0);
                    uint32_t off1 = swz128((uint32_t)key * 128u + col0 + 32u);
                    uint32_t v00, v01, v02, v03, v10, v11, v12, v13;
                    ldsm4t(v00, v01, v02, v03, kvb + 16384u + off0);
                    ldsm4t(v10, v11, v12, v13, kvb + 16384u + off1);
                    mma_f16(oc[4 * dpp + 0], pf, v00, v01);
                    mma_f16(oc[4 * dpp + 1], pf, v02, v03);
                    mma_f16(oc[4 * dpp + 2], pf, v10, v11);
                    mma_f16(oc[4 * dpp + 3], pf, v12, v13);
                }
            }
        }
        rbuf = rbuf + 1; if (rbuf == 3) rbuf = 0;
    }
#undef ISSUE_KV

    // lsC[0] = lsum(row0), lsC[2] = lsum(row1)
    float inv0 = 1.f / lsC[0], inv1 = 1.f / lsC[2];

    // store ctx as fp16 (gemm1 input)
    int b = bh >> 3, h = bh & 7;
    size_t r0base = (size_t)(b * L_ + row0) * HIDDEN + h * 64;
    size_t r1base = (size_t)(b * L_ + row1) * HIDDEN + h * 64;
#pragma unroll
    for (int n = 0; n < 8; n++) {
        int d = 8 * n + 2 * (lane & 3);
        *(uint32_t*)(gctx_f16 + r0base + d) = cvt_f16x2(oc[n][0] * inv0, oc[n][1] * inv0);
        *(uint32_t*)(gctx_f16 + r1base + d) = cvt_f16x2(oc[n][2] * inv1, oc[n][3] * inv1);
    }
}

// ============================================================
extern "C" void kernel_launch(void* const* d_in, const int* in_sizes, int n_in,
                              void* d_out, int out_size)
{
    const float* x     = (const float*)d_in[0];
    const float* w_in  = (const float*)d_in[1];
    const float* b_in  = (const float*)d_in[2];
    const float* w_out = (const float*)d_in[3];
    const float* b_out = (const float*)d_in[4];
    float* out = (float*)d_out;

    conv_x_kernel<<<(M_ROWS * HIDDEN / 4) / 256, 256>>>(x);
    conv_wT_kernel<<<dim3(3 * HIDDEN / 32, HIDDEN / 32), 256>>>(w_in, HIDDEN, 3 * HIDDEN, 0);
    conv_wT_kernel<<<dim3(HIDDEN / 32, HIDDEN / 32), 256>>>(w_out, HIDDEN, HIDDEN, 1);

    cudaFuncSetAttribute(gemm_f16_kernel<0>,
                         cudaFuncAttributeMaxDynamicSharedMemorySize, 3 * GSTAGE);
    gemm_f16_kernel<0><<<dim3(12, 64), 256, 3 * GSTAGE>>>(b_in, nullptr);

    cudaFuncSetAttribute(attn_mma_kernel,
                         cudaFuncAttributeMaxDynamicSharedMemorySize, ATTN_SMEM);
    attn_mma_kernel<<<dim3(16, 32), 256, ATTN_SMEM>>>();

    cudaFuncSetAttribute(gemm_f16_kernel<1>,
                         cudaFuncAttributeMaxDynamicSharedMemorySize, 3 * GSTAGE);
    gemm_f16_kernel<1><<<dim3(4, 64), 256, 3 * GSTAGE>>>(b_out, out);
}